// round 1
// baseline (speedup 1.0000x reference)
#include <cuda_runtime.h>
#include <math.h>

#define BB   32
#define LQ   512
#define DD   384
#define FF   384
#define MROWS (BB*LQ)      // 16384
#define KDIM  (DD*3)       // 1152
#define LN_EPS 1e-5f

// Scratch (no allocations allowed): two ping-pong activation buffers + cumsum.
__device__ float g_buf1[(size_t)MROWS * FF];   // 25.2 MB
__device__ float g_buf2[(size_t)MROWS * FF];   // 25.2 MB
__device__ int   g_cum[BB * LQ];

// ---------------------------------------------------------------------------
// Conv-as-GEMM with implicit im2col.
//   Y[m][f] = sum_{kk<1152} A(m,kk) * W[f*1152 + kk] + bias[f]
//   A(m,kk): m=(b,l), kk=(d,k) with kk = d*3+k, value = X[b, l+k-1, d] (0-pad).
// X and Y are [B*L, 384] row-major. 64x64 tile, BK=16, 256 threads, 4x4 micro.
// ---------------------------------------------------------------------------
__global__ __launch_bounds__(256) void conv_gemm_kernel(
    const float* __restrict__ X, const float* __restrict__ W,
    const float* __restrict__ bias, float* __restrict__ Y)
{
    __shared__ float As[16][68];   // [kk][m] (68 = 64 + 4 pad, keeps 16B align)
    __shared__ float Bs[16][68];   // [kk][f]

    const int m0 = blockIdx.x * 64;
    const int f0 = blockIdx.y * 64;
    const int t  = threadIdx.x;          // 0..255
    const int tx = t & 15, ty = t >> 4;  // 16x16 thread grid, 4x4 per thread

    // Loader mapping: each thread loads 4 consecutive kk for one row.
    const int a_row = t >> 2;            // 0..63
    const int a_cb  = (t & 3) * 4;       // 0,4,8,12

    const int m = m0 + a_row;
    const int b = m >> 9;                // /512
    const int l = m & 511;

    float acc[4][4] = {};

    for (int kk0 = 0; kk0 < KDIM; kk0 += 16) {
        // --- A tile (implicit im2col) ---
        #pragma unroll
        for (int j = 0; j < 4; j++) {
            int kk = kk0 + a_cb + j;
            int d  = kk / 3;
            int k  = kk - d * 3;
            int l2 = l + k - 1;
            float v = 0.0f;
            if (l2 >= 0 && l2 < LQ)
                v = X[(size_t)(((b << 9) + l2)) * DD + d];
            As[a_cb + j][a_row] = v;
        }
        // --- B tile: W^T, vectorized (W rows are 1152 floats, 16B aligned) ---
        const float4 wv = *(const float4*)(W + (size_t)(f0 + a_row) * KDIM + kk0 + a_cb);
        Bs[a_cb + 0][a_row] = wv.x;
        Bs[a_cb + 1][a_row] = wv.y;
        Bs[a_cb + 2][a_row] = wv.z;
        Bs[a_cb + 3][a_row] = wv.w;
        __syncthreads();

        #pragma unroll
        for (int kk = 0; kk < 16; kk++) {
            float4 ra = *(const float4*)&As[kk][ty * 4];
            float4 rb = *(const float4*)&Bs[kk][tx * 4];
            float a_[4] = {ra.x, ra.y, ra.z, ra.w};
            float b_[4] = {rb.x, rb.y, rb.z, rb.w};
            #pragma unroll
            for (int i = 0; i < 4; i++)
                #pragma unroll
                for (int j = 0; j < 4; j++)
                    acc[i][j] += a_[i] * b_[j];
        }
        __syncthreads();
    }

    #pragma unroll
    for (int i = 0; i < 4; i++) {
        const int mm = m0 + ty * 4 + i;
        #pragma unroll
        for (int j = 0; j < 4; j++) {
            const int ff = f0 + tx * 4 + j;
            Y[(size_t)mm * FF + ff] = acc[i][j] + bias[ff];
        }
    }
}

// ---------------------------------------------------------------------------
// Block-wide reduction of (sum, sumsq). 128 threads = 4 warps.
// ---------------------------------------------------------------------------
__device__ __forceinline__ float2 block_reduce2(float s, float q)
{
    __shared__ float sh[8];
    __syncthreads();   // protect against reuse across sequential calls
    const int lane = threadIdx.x & 31;
    const int w    = threadIdx.x >> 5;
    #pragma unroll
    for (int o = 16; o > 0; o >>= 1) {
        s += __shfl_down_sync(0xffffffffu, s, o);
        q += __shfl_down_sync(0xffffffffu, q, o);
    }
    if (lane == 0) { sh[w] = s; sh[4 + w] = q; }
    __syncthreads();
    if (threadIdx.x == 0) {
        sh[0] = sh[0] + sh[1] + sh[2] + sh[3];
        sh[4] = sh[4] + sh[5] + sh[6] + sh[7];
    }
    __syncthreads();
    return make_float2(sh[0], sh[4]);
}

// LayerNorm + ReLU, one block (128 thr) per row of 384.
__global__ __launch_bounds__(128) void ln_relu_kernel(
    const float* __restrict__ In, const float* __restrict__ gam,
    const float* __restrict__ bet, float* __restrict__ Out)
{
    const int row = blockIdx.x;
    const int t   = threadIdx.x;
    const float* p = In + (size_t)row * FF;
    float v0 = p[t], v1 = p[t + 128], v2 = p[t + 256];
    float2 r = block_reduce2(v0 + v1 + v2, v0 * v0 + v1 * v1 + v2 * v2);
    const float mu  = r.x * (1.0f / FF);
    const float var = r.y * (1.0f / FF) - mu * mu;
    const float rs  = rsqrtf(var + LN_EPS);
    float* o = Out + (size_t)row * FF;
    float v[3] = {v0, v1, v2};
    #pragma unroll
    for (int i = 0; i < 3; i++) {
        const int f = t + i * 128;
        o[f] = fmaxf((v[i] - mu) * rs * gam[f] + bet[f], 0.0f);
    }
}

// LayerNorm + ReLU + linear(384->1) + ReLU, fused: never materializes h2.
__global__ __launch_bounds__(128) void ln_linear_kernel(
    const float* __restrict__ In, const float* __restrict__ gam,
    const float* __restrict__ bet, const float* __restrict__ lw,
    const float* __restrict__ lb, float* __restrict__ dur)
{
    const int row = blockIdx.x;
    const int t   = threadIdx.x;
    const float* p = In + (size_t)row * FF;
    float v0 = p[t], v1 = p[t + 128], v2 = p[t + 256];
    float2 r = block_reduce2(v0 + v1 + v2, v0 * v0 + v1 * v1 + v2 * v2);
    const float mu  = r.x * (1.0f / FF);
    const float var = r.y * (1.0f / FF) - mu * mu;
    const float rs  = rsqrtf(var + LN_EPS);
    float v[3] = {v0, v1, v2};
    float acc = 0.0f;
    #pragma unroll
    for (int i = 0; i < 3; i++) {
        const int f = t + i * 128;
        float h = fmaxf((v[i] - mu) * rs * gam[f] + bet[f], 0.0f);
        acc += h * lw[f];
    }
    float2 r2 = block_reduce2(acc, 0.0f);
    if (t == 0) dur[row] = fmaxf(r2.x + lb[0], 0.0f);
}

// Inclusive scan of target durations, one block (512 thr) per batch.
__global__ __launch_bounds__(512) void scan_kernel(const int* __restrict__ target)
{
    __shared__ int s[512];
    const int b = blockIdx.x, t = threadIdx.x;
    s[t] = target[b * LQ + t];
    __syncthreads();
    for (int off = 1; off < 512; off <<= 1) {
        int v = (t >= off) ? s[t - off] : 0;
        __syncthreads();
        s[t] += v;
        __syncthreads();
    }
    g_cum[b * LQ + t] = s[t];
}

// Expand: one block (96 thr, float4) per output frame (b, t).
__global__ __launch_bounds__(96) void expand_kernel(
    const float* __restrict__ X, float* __restrict__ out, int M)
{
    const int tfr = blockIdx.x;
    const int b   = blockIdx.y;
    const int* cum = g_cum + b * LQ;
    float4* dst = (float4*)(out + ((size_t)b * M + tfr) * DD);
    const int total = cum[LQ - 1];
    if (tfr >= total) {
        dst[threadIdx.x] = make_float4(0.f, 0.f, 0.f, 0.f);
        return;
    }
    // searchsorted(cum, t, 'right'): first i with cum[i] > t
    int lo = 0, hi = LQ;
    while (lo < hi) {
        int mid = (lo + hi) >> 1;
        if (cum[mid] <= tfr) lo = mid + 1; else hi = mid;
    }
    const int idx = min(lo, LQ - 1);
    const float4* src = (const float4*)(X + ((size_t)b * LQ + idx) * DD);
    dst[threadIdx.x] = src[threadIdx.x];
}

// ---------------------------------------------------------------------------
extern "C" void kernel_launch(void* const* d_in, const int* in_sizes, int n_in,
                              void* d_out, int out_size)
{
    const float* x     = (const float*)d_in[0];
    const float* c1_w  = (const float*)d_in[1];
    const float* c1_b  = (const float*)d_in[2];
    const float* ln1_g = (const float*)d_in[3];
    const float* ln1_b = (const float*)d_in[4];
    const float* c2_w  = (const float*)d_in[5];
    const float* c2_b  = (const float*)d_in[6];
    const float* ln2_g = (const float*)d_in[7];
    const float* ln2_b = (const float*)d_in[8];
    const float* lin_w = (const float*)d_in[9];
    const float* lin_b = (const float*)d_in[10];
    const int*   target= (const int*)d_in[11];

    // mel_max_length derived from out_size (out = [B,M,D] then dur = [B,L]).
    const int M = (out_size - BB * LQ) / (BB * DD);

    float* buf1; cudaGetSymbolAddress((void**)&buf1, g_buf1);
    float* buf2; cudaGetSymbolAddress((void**)&buf2, g_buf2);

    float* out_expand = (float*)d_out;
    float* out_dur    = (float*)d_out + (size_t)BB * M * DD;

    dim3 gemm_grid(MROWS / 64, FF / 64);

    // Duration predictor
    conv_gemm_kernel<<<gemm_grid, 256>>>(x, c1_w, c1_b, buf1);
    ln_relu_kernel<<<MROWS, 128>>>(buf1, ln1_g, ln1_b, buf2);
    conv_gemm_kernel<<<gemm_grid, 256>>>(buf2, c2_w, c2_b, buf1);
    ln_linear_kernel<<<MROWS, 128>>>(buf1, ln2_g, ln2_b, lin_w, lin_b, out_dur);

    // Expand path
    scan_kernel<<<BB, 512>>>(target);
    expand_kernel<<<dim3(M, BB), 96>>>(x, out_expand, M);
}

// round 2
// speedup vs baseline: 2.3259x; 2.3259x over previous
#include <cuda_runtime.h>
#include <math.h>

#define BB   32
#define LQ   512
#define DD   384
#define FF   384
#define MROWS (BB*LQ)      // 16384
#define KDIM  (DD*3)       // 1152
#define LN_EPS 1e-5f

// Scratch (no allocations allowed).
__device__ float g_buf1[(size_t)MROWS * FF];   // 25.2 MB
__device__ float g_buf2[(size_t)MROWS * FF];   // 25.2 MB
__device__ float g_w1r[(size_t)FF * KDIM];     // 1.7 MB reordered c1_w
__device__ float g_w2r[(size_t)FF * KDIM];     // 1.7 MB reordered c2_w
__device__ int   g_cum[BB * LQ];

// ---------------------------------------------------------------------------
// Reorder W: Wr[f][k*384+d] = W[f][d*3+k]   (im2col K-dim becomes k-major)
// ---------------------------------------------------------------------------
__global__ __launch_bounds__(256) void reorder_w_kernel(
    const float* __restrict__ W, float* __restrict__ Wr)
{
    const int f = blockIdx.x;
    for (int i = threadIdx.x; i < KDIM; i += 256) {
        const int k = i / DD;
        const int d = i - k * DD;
        Wr[(size_t)f * KDIM + i] = W[(size_t)f * KDIM + d * 3 + k];
    }
}

__device__ __forceinline__ unsigned f2tf(float f)
{
    unsigned r;
    asm("cvt.rna.tf32.f32 %0, %1;" : "=r"(r) : "f"(f));
    return r;
}

__device__ __forceinline__ void mma_tf32(float c[4], const unsigned a[4],
                                         const unsigned b[2])
{
    asm volatile(
        "mma.sync.aligned.m16n8k8.row.col.f32.tf32.tf32.f32 "
        "{%0,%1,%2,%3}, {%4,%5,%6,%7}, {%8,%9}, {%0,%1,%2,%3};"
        : "+f"(c[0]), "+f"(c[1]), "+f"(c[2]), "+f"(c[3])
        : "r"(a[0]), "r"(a[1]), "r"(a[2]), "r"(a[3]), "r"(b[0]), "r"(b[1]));
}

// ---------------------------------------------------------------------------
// Conv-as-GEMM on tensor cores (tf32 mma.sync), implicit im2col with k-major
// K ordering:  Y[m][f] = sum_{k,d} X[b, l+k-1, d] * Wr[f][k*384+d] + bias[f]
// CTA tile 128x64, BK=16, 256 threads, warp grid 2(m) x 4(n), warp tile 64x16.
// ---------------------------------------------------------------------------
__global__ __launch_bounds__(256) void conv_mma_kernel(
    const float* __restrict__ X, const float* __restrict__ Wr,
    const float* __restrict__ bias, float* __restrict__ Y)
{
    __shared__ float As[2][128][20];   // stride 20: conflict-free frag loads
    __shared__ float Bs[2][64][20];

    const int m0 = blockIdx.x * 128;
    const int f0 = blockIdx.y * 64;
    const int t  = threadIdx.x;

    const int lane = t & 31;
    const int grp  = lane >> 2;     // 0..7
    const int tig  = lane & 3;      // 0..3
    const int warp = t >> 5;
    const int m_base = (warp & 1) * 64;
    const int n_base = (warp >> 1) * 16;

    // global->smem loader mapping
    const int row_a0 = t >> 2;          // 0..63
    const int row_a1 = row_a0 + 64;     // 64..127
    const int col4   = (t & 3) * 4;     // 0,4,8,12

    const int mA0 = m0 + row_a0, mA1 = m0 + row_a1;
    const int bA0 = mA0 >> 9, lA0 = mA0 & 511;
    const int bA1 = mA1 >> 9, lA1 = mA1 & 511;

    float acc[4][2][4] = {};

    // ---- preload iter 0 ----
    {
        const int kk0 = 0;                 // kseg = 0, d0 = col4
        const int l20 = lA0 - 1, l21 = lA1 - 1;
        float4 pa0 = make_float4(0,0,0,0), pa1 = make_float4(0,0,0,0);
        if (l20 >= 0) pa0 = *(const float4*)&X[((size_t)(bA0 << 9) + l20) * DD + col4];
        if (l21 >= 0) pa1 = *(const float4*)&X[((size_t)(bA1 << 9) + l21) * DD + col4];
        float4 pb = *(const float4*)&Wr[(size_t)(f0 + row_a0) * KDIM + kk0 + col4];
        float4* da0 = (float4*)&As[0][row_a0][col4];
        float4* da1 = (float4*)&As[0][row_a1][col4];
        float4* db  = (float4*)&Bs[0][row_a0][col4];
        da0->x = __uint_as_float(f2tf(pa0.x)); da0->y = __uint_as_float(f2tf(pa0.y));
        da0->z = __uint_as_float(f2tf(pa0.z)); da0->w = __uint_as_float(f2tf(pa0.w));
        da1->x = __uint_as_float(f2tf(pa1.x)); da1->y = __uint_as_float(f2tf(pa1.y));
        da1->z = __uint_as_float(f2tf(pa1.z)); da1->w = __uint_as_float(f2tf(pa1.w));
        db->x  = __uint_as_float(f2tf(pb.x));  db->y  = __uint_as_float(f2tf(pb.y));
        db->z  = __uint_as_float(f2tf(pb.z));  db->w  = __uint_as_float(f2tf(pb.w));
    }
    __syncthreads();

    const int NIT = KDIM / 16;   // 72
    for (int it = 0; it < NIT; ++it) {
        const bool has = (it + 1 < NIT);
        float4 pa0 = make_float4(0,0,0,0), pa1 = make_float4(0,0,0,0);
        float4 pb  = make_float4(0,0,0,0);
        if (has) {
            const int kk0  = (it + 1) * 16;
            const int kseg = kk0 / DD;            // 0,1,2
            const int d0   = kk0 - kseg * DD + col4;
            const int l20  = lA0 + kseg - 1;
            const int l21  = lA1 + kseg - 1;
            if (l20 >= 0 && l20 < LQ)
                pa0 = *(const float4*)&X[((size_t)(bA0 << 9) + l20) * DD + d0];
            if (l21 >= 0 && l21 < LQ)
                pa1 = *(const float4*)&X[((size_t)(bA1 << 9) + l21) * DD + d0];
            pb = *(const float4*)&Wr[(size_t)(f0 + row_a0) * KDIM + kk0 + col4];
        }

        // ---- compute on buffer it&1 ----
        const int buf = it & 1;
        #pragma unroll
        for (int ks = 0; ks < 2; ++ks) {
            const int col = ks * 8 + tig;
            unsigned bf[2][2];
            #pragma unroll
            for (int nt = 0; nt < 2; ++nt) {
                const int br = n_base + nt * 8 + grp;
                bf[nt][0] = __float_as_uint(Bs[buf][br][col]);
                bf[nt][1] = __float_as_uint(Bs[buf][br][col + 4]);
            }
            #pragma unroll
            for (int mt = 0; mt < 4; ++mt) {
                const int ar = m_base + mt * 16 + grp;
                unsigned af[4];
                af[0] = __float_as_uint(As[buf][ar][col]);
                af[1] = __float_as_uint(As[buf][ar + 8][col]);
                af[2] = __float_as_uint(As[buf][ar][col + 4]);
                af[3] = __float_as_uint(As[buf][ar + 8][col + 4]);
                #pragma unroll
                for (int nt = 0; nt < 2; ++nt)
                    mma_tf32(acc[mt][nt], af, bf[nt]);
            }
        }

        if (has) {
            const int nb = (it + 1) & 1;
            float4* da0 = (float4*)&As[nb][row_a0][col4];
            float4* da1 = (float4*)&As[nb][row_a1][col4];
            float4* db  = (float4*)&Bs[nb][row_a0][col4];
            da0->x = __uint_as_float(f2tf(pa0.x)); da0->y = __uint_as_float(f2tf(pa0.y));
            da0->z = __uint_as_float(f2tf(pa0.z)); da0->w = __uint_as_float(f2tf(pa0.w));
            da1->x = __uint_as_float(f2tf(pa1.x)); da1->y = __uint_as_float(f2tf(pa1.y));
            da1->z = __uint_as_float(f2tf(pa1.z)); da1->w = __uint_as_float(f2tf(pa1.w));
            db->x  = __uint_as_float(f2tf(pb.x));  db->y  = __uint_as_float(f2tf(pb.y));
            db->z  = __uint_as_float(f2tf(pb.z));  db->w  = __uint_as_float(f2tf(pb.w));
        }
        __syncthreads();
    }

    // ---- epilogue: bias + store ----
    #pragma unroll
    for (int mt = 0; mt < 4; ++mt) {
        const int mrow = m0 + m_base + mt * 16 + grp;
        #pragma unroll
        for (int nt = 0; nt < 2; ++nt) {
            const int fc = f0 + n_base + nt * 8 + 2 * tig;
            const float b0v = bias[fc], b1v = bias[fc + 1];
            float2 r0 = make_float2(acc[mt][nt][0] + b0v, acc[mt][nt][1] + b1v);
            float2 r1 = make_float2(acc[mt][nt][2] + b0v, acc[mt][nt][3] + b1v);
            *(float2*)&Y[(size_t)mrow * FF + fc] = r0;
            *(float2*)&Y[(size_t)(mrow + 8) * FF + fc] = r1;
        }
    }
}

// ---------------------------------------------------------------------------
// Block-wide reduction of (sum, sumsq). 128 threads = 4 warps.
// ---------------------------------------------------------------------------
__device__ __forceinline__ float2 block_reduce2(float s, float q)
{
    __shared__ float sh[8];
    __syncthreads();
    const int lane = threadIdx.x & 31;
    const int w    = threadIdx.x >> 5;
    #pragma unroll
    for (int o = 16; o > 0; o >>= 1) {
        s += __shfl_down_sync(0xffffffffu, s, o);
        q += __shfl_down_sync(0xffffffffu, q, o);
    }
    if (lane == 0) { sh[w] = s; sh[4 + w] = q; }
    __syncthreads();
    if (threadIdx.x == 0) {
        sh[0] = sh[0] + sh[1] + sh[2] + sh[3];
        sh[4] = sh[4] + sh[5] + sh[6] + sh[7];
    }
    __syncthreads();
    return make_float2(sh[0], sh[4]);
}

__global__ __launch_bounds__(128) void ln_relu_kernel(
    const float* __restrict__ In, const float* __restrict__ gam,
    const float* __restrict__ bet, float* __restrict__ Out)
{
    const int row = blockIdx.x;
    const int t   = threadIdx.x;
    const float* p = In + (size_t)row * FF;
    float v0 = p[t], v1 = p[t + 128], v2 = p[t + 256];
    float2 r = block_reduce2(v0 + v1 + v2, v0 * v0 + v1 * v1 + v2 * v2);
    const float mu  = r.x * (1.0f / FF);
    const float var = r.y * (1.0f / FF) - mu * mu;
    const float rs  = rsqrtf(var + LN_EPS);
    float* o = Out + (size_t)row * FF;
    float v[3] = {v0, v1, v2};
    #pragma unroll
    for (int i = 0; i < 3; i++) {
        const int f = t + i * 128;
        o[f] = fmaxf((v[i] - mu) * rs * gam[f] + bet[f], 0.0f);
    }
}

__global__ __launch_bounds__(128) void ln_linear_kernel(
    const float* __restrict__ In, const float* __restrict__ gam,
    const float* __restrict__ bet, const float* __restrict__ lw,
    const float* __restrict__ lb, float* __restrict__ dur)
{
    const int row = blockIdx.x;
    const int t   = threadIdx.x;
    const float* p = In + (size_t)row * FF;
    float v0 = p[t], v1 = p[t + 128], v2 = p[t + 256];
    float2 r = block_reduce2(v0 + v1 + v2, v0 * v0 + v1 * v1 + v2 * v2);
    const float mu  = r.x * (1.0f / FF);
    const float var = r.y * (1.0f / FF) - mu * mu;
    const float rs  = rsqrtf(var + LN_EPS);
    float v[3] = {v0, v1, v2};
    float acc = 0.0f;
    #pragma unroll
    for (int i = 0; i < 3; i++) {
        const int f = t + i * 128;
        float h = fmaxf((v[i] - mu) * rs * gam[f] + bet[f], 0.0f);
        acc += h * lw[f];
    }
    float2 r2 = block_reduce2(acc, 0.0f);
    if (t == 0) dur[row] = fmaxf(r2.x + lb[0], 0.0f);
}

__global__ __launch_bounds__(512) void scan_kernel(const int* __restrict__ target)
{
    __shared__ int s[512];
    const int b = blockIdx.x, t = threadIdx.x;
    s[t] = target[b * LQ + t];
    __syncthreads();
    for (int off = 1; off < 512; off <<= 1) {
        int v = (t >= off) ? s[t - off] : 0;
        __syncthreads();
        s[t] += v;
        __syncthreads();
    }
    g_cum[b * LQ + t] = s[t];
}

__global__ __launch_bounds__(96) void expand_kernel(
    const float* __restrict__ X, float* __restrict__ out, int M)
{
    const int tfr = blockIdx.x;
    const int b   = blockIdx.y;
    const int* cum = g_cum + b * LQ;
    float4* dst = (float4*)(out + ((size_t)b * M + tfr) * DD);
    const int total = cum[LQ - 1];
    if (tfr >= total) {
        dst[threadIdx.x] = make_float4(0.f, 0.f, 0.f, 0.f);
        return;
    }
    int lo = 0, hi = LQ;
    while (lo < hi) {
        int mid = (lo + hi) >> 1;
        if (cum[mid] <= tfr) lo = mid + 1; else hi = mid;
    }
    const int idx = min(lo, LQ - 1);
    const float4* src = (const float4*)(X + ((size_t)b * LQ + idx) * DD);
    dst[threadIdx.x] = src[threadIdx.x];
}

// ---------------------------------------------------------------------------
extern "C" void kernel_launch(void* const* d_in, const int* in_sizes, int n_in,
                              void* d_out, int out_size)
{
    const float* x     = (const float*)d_in[0];
    const float* c1_w  = (const float*)d_in[1];
    const float* c1_b  = (const float*)d_in[2];
    const float* ln1_g = (const float*)d_in[3];
    const float* ln1_b = (const float*)d_in[4];
    const float* c2_w  = (const float*)d_in[5];
    const float* c2_b  = (const float*)d_in[6];
    const float* ln2_g = (const float*)d_in[7];
    const float* ln2_b = (const float*)d_in[8];
    const float* lin_w = (const float*)d_in[9];
    const float* lin_b = (const float*)d_in[10];
    const int*   target= (const int*)d_in[11];

    const int M = (out_size - BB * LQ) / (BB * DD);

    float* buf1; cudaGetSymbolAddress((void**)&buf1, g_buf1);
    float* buf2; cudaGetSymbolAddress((void**)&buf2, g_buf2);
    float* w1r;  cudaGetSymbolAddress((void**)&w1r,  g_w1r);
    float* w2r;  cudaGetSymbolAddress((void**)&w2r,  g_w2r);

    float* out_expand = (float*)d_out;
    float* out_dur    = (float*)d_out + (size_t)BB * M * DD;

    dim3 gemm_grid(MROWS / 128, FF / 64);

    // Weight reorders (cheap; inside the graph, deterministic)
    reorder_w_kernel<<<FF, 256>>>(c1_w, w1r);
    reorder_w_kernel<<<FF, 256>>>(c2_w, w2r);

    // Duration predictor (tensor-core tf32 GEMMs)
    conv_mma_kernel<<<gemm_grid, 256>>>(x, w1r, c1_b, buf1);
    ln_relu_kernel<<<MROWS, 128>>>(buf1, ln1_g, ln1_b, buf2);
    conv_mma_kernel<<<gemm_grid, 256>>>(buf2, w2r, c2_b, buf1);
    ln_linear_kernel<<<MROWS, 128>>>(buf1, ln2_g, ln2_b, lin_w, lin_b, out_dur);

    // Expand path
    scan_kernel<<<BB, 512>>>(target);
    expand_kernel<<<dim3(M, BB), 96>>>(x, out_expand, M);
}